// round 12
// baseline (speedup 1.0000x reference)
#include <cuda_runtime.h>
#include <cuda_fp16.h>
#include <cstdint>

#define NB  8
#define SL  2048
#define DIM 128
#define BQ  128
#define BK  64
#define NT  (SL / BK)     // 32 K-tiles

// smem byte strides
#define RQ  288           // Q/K row: 128 halves (256B) + 32B pad
#define RV  160           // Vt row: 64 halves (128B) + 32B pad

// attn smem byte offsets (all 16B aligned). Total 152,064 B -> 1 CTA/SM.
#define OQH 0
#define OKH (OQH + BQ * RQ)            // 36864  (2 bufs x 64*288)
#define OKL (OKH + 2 * BK * RQ)        // 73728
#define OVT (OKL + 2 * BK * RQ)        // 110592 (2 bufs x 128*160)
#define OMK (OVT + 2 * DIM * RV)       // 151552 (2 x 256B)
#define SMEM_ATTN (OMK + 2 * 256)      // 152064

// proj_qk_mma smem offsets: Xhi/Xlo/Whi/Wlo, each 128 rows x RQ bytes
#define PXH 0
#define PXL (PXH + 128 * RQ)           // 36864
#define PWH (PXL + 128 * RQ)           // 73728
#define PWL (PWH + 128 * RQ)           // 110592
#define SMEM_PROJQK (PWL + 128 * RQ)   // 147456

// Projected tensors: Q hi-only; K hi+lo fp16 split; V transposed half.
__device__ __half g_qhi[NB * SL * DIM];
__device__ __half g_khi[NB * SL * DIM];
__device__ __half g_klo[NB * SL * DIM];
__device__ __half g_vt [NB * DIM * SL];   // [b][dim][key], key pair-permuted

// Pre-transposed, pre-split weights: [sel][n*128 + kpos], dense 256B rows.
__device__ __half g_wth[2][DIM * DIM];
__device__ __half g_wtl[2][DIM * DIM];

__device__ __forceinline__ uint32_t h2u(__half2 h) {
    return *reinterpret_cast<uint32_t*>(&h);
}
__device__ __forceinline__ void cpa16(uint32_t saddr, const void* gaddr) {
    asm volatile("cp.async.ca.shared.global [%0], [%1], 16;\n"
                 :: "r"(saddr), "l"(gaddr));
}
__device__ __forceinline__ void cpa_commit() {
    asm volatile("cp.async.commit_group;\n" ::: "memory");
}

#define MMA16(C, A0, A1, A2, A3, B0, B1)                                     \
    asm volatile(                                                            \
        "mma.sync.aligned.m16n8k16.row.col.f32.f16.f16.f32 "                 \
        "{%0,%1,%2,%3},{%4,%5,%6,%7},{%8,%9},{%0,%1,%2,%3};"                 \
        : "+f"(C[0]), "+f"(C[1]), "+f"(C[2]), "+f"(C[3])                     \
        : "r"(A0), "r"(A1), "r"(A2), "r"(A3), "r"(B0), "r"(B1))

// Pair permutation within a 16-col chunk: pair p (cols 2p,2p+1) -> word w.
__host__ __device__ __forceinline__ int permw(int p) {
    return (p < 4) ? (2 * p) : (2 * (p - 4) + 1);
}

// ---------------------------------------------------------------------------
// One-time weight prep: transpose + fp16 hi/lo split of Wq/Wk into the exact
// row layout proj_qk_mma's B-fragments read. Tiny (2 x 64KB), L2-resident.
// ---------------------------------------------------------------------------
__global__ __launch_bounds__(256, 1)
void prep_w(const float* __restrict__ Wq, const float* __restrict__ Wk) {
    const int sel = blockIdx.x;
    const float* W = sel ? Wk : Wq;
    const int tid = threadIdx.x;
    for (int i = tid; i < 128 * 32; i += 256) {
        int k = i >> 5, n0 = (i & 31) << 2;
        float4 v = *(const float4*)&W[k * DIM + n0];
        int kpos = ((k >> 4) << 4) + (permw((k & 15) >> 1) << 1) + (k & 1);
        float y[4] = {v.x, v.y, v.z, v.w};
#pragma unroll
        for (int j = 0; j < 4; j++) {
            __half hi = __float2half_rn(y[j]);
            g_wth[sel][(n0 + j) * DIM + kpos] = hi;
            g_wtl[sel][(n0 + j) * DIM + kpos] =
                __float2half_rn(y[j] - __half2float(hi));
        }
    }
}

// ---------------------------------------------------------------------------
// Q/K projection on tensor cores. CTA = 128 rows x 128 cols, K=128.
// W arrives pre-transposed/split via cp.async (conflict-free). X loaded as
// fp32, split hi/lo into pair-permuted smem. Y = Xhi*Whi + Xlo*Whi + Xhi*Wlo.
// ---------------------------------------------------------------------------
__global__ __launch_bounds__(256, 1)
void proj_qk_mma(const float* __restrict__ Xq, const float* __restrict__ Xk) {
    extern __shared__ char smem[];
    const uint32_t sb = (uint32_t)__cvta_generic_to_shared(smem);
    const int sel = blockIdx.x >> 7;
    const int blk = blockIdx.x & 127;
    const float* X = sel ? Xk : Xq;

    const int tid = threadIdx.x;
    const long r0 = (long)blk * 128;

    // ---- W hi/lo via cp.async: row n = 256B = 16 chunks ----
    for (int i = tid; i < 2 * 128 * 16; i += 256) {
        int half_sel = i >> 11;            // 0 = hi, 1 = lo
        int j = i & 2047, n = j >> 4, c = j & 15;
        const __half* src = (half_sel ? g_wtl[sel] : g_wth[sel]) + n * DIM + c * 8;
        cpa16(sb + (half_sel ? PWL : PWH) + n * RQ + c * 16, src);
    }
    cpa_commit();

    // ---- X [128 x 128] fp32 -> hi/lo halves, pair-permuted dims ----
    for (int i = tid; i < 128 * 32; i += 256) {
        int row = i >> 5, d0 = (i & 31) << 2;
        float4 v = *(const float4*)&X[(r0 + row) * DIM + d0];
        __half2 h01 = __floats2half2_rn(v.x, v.y);
        __half2 h23 = __floats2half2_rn(v.z, v.w);
        float2 f01 = __half22float2(h01), f23 = __half22float2(h23);
        __half2 l01 = __floats2half2_rn(v.x - f01.x, v.y - f01.y);
        __half2 l23 = __floats2half2_rn(v.z - f23.x, v.w - f23.y);
        int p0 = (d0 & 15) >> 1;              // {0,2,4,6}
        int base = row * RQ + (d0 >> 4) * 32;
        int o0 = base + permw(p0) * 4;
        int o1 = base + permw(p0 + 1) * 4;
        *(uint32_t*)(smem + PXH + o0) = h2u(h01);
        *(uint32_t*)(smem + PXH + o1) = h2u(h23);
        *(uint32_t*)(smem + PXL + o0) = h2u(l01);
        *(uint32_t*)(smem + PXL + o1) = h2u(l23);
    }
    asm volatile("cp.async.wait_group 0;\n" ::: "memory");
    __syncthreads();

    const int w    = tid >> 5;
    const int lane = tid & 31;
    const int g    = lane >> 2;
    const int t    = lane & 3;
    const int qrow = (w << 4) + g;

    const char* xh0 = smem + PXH + qrow * RQ;
    const char* xh1 = xh0 + 8 * RQ;
    const char* xl0 = smem + PXL + qrow * RQ;
    const char* xl1 = xl0 + 8 * RQ;

    float c[16][4];
#pragma unroll
    for (int n = 0; n < 16; n++)
#pragma unroll
        for (int j = 0; j < 4; j++) c[n][j] = 0.f;

#pragma unroll
    for (int kc = 0; kc < 8; kc++) {
        const int off = kc * 32 + t * 8;
        uint2 a0 = *(const uint2*)(xh0 + off);
        uint2 a1 = *(const uint2*)(xh1 + off);
        uint2 e0 = *(const uint2*)(xl0 + off);
        uint2 e1 = *(const uint2*)(xl1 + off);
        // pass 1: Xhi * Whi
#pragma unroll
        for (int nt = 0; nt < 16; nt++) {
            uint2 bh = *(const uint2*)(smem + PWH + (nt * 8 + g) * RQ + off);
            MMA16(c[nt], a0.x, a1.x, a0.y, a1.y, bh.x, bh.y);
        }
        // pass 2: Xlo * Whi
#pragma unroll
        for (int nt = 0; nt < 16; nt++) {
            uint2 bh = *(const uint2*)(smem + PWH + (nt * 8 + g) * RQ + off);
            MMA16(c[nt], e0.x, e1.x, e0.y, e1.y, bh.x, bh.y);
        }
        // pass 3: Xhi * Wlo
#pragma unroll
        for (int nt = 0; nt < 16; nt++) {
            uint2 bl = *(const uint2*)(smem + PWL + (nt * 8 + g) * RQ + off);
            MMA16(c[nt], a0.x, a1.x, a0.y, a1.y, bl.x, bl.y);
        }
    }

    // ---- store: frag col n = 8nt+2t+h -> permuted position ----
    __half* Yh = sel ? g_khi : g_qhi;
#pragma unroll
    for (int nt = 0; nt < 16; nt++) {
        int colb = ((nt >> 1) << 4) + 4 * t + ((nt & 1) << 1);
        long i0 = (r0 + qrow) * DIM + colb;
        long i1 = (r0 + qrow + 8) * DIM + colb;
        __half2 hA = __floats2half2_rn(c[nt][0], c[nt][1]);
        __half2 hB = __floats2half2_rn(c[nt][2], c[nt][3]);
        *(__half2*)&Yh[i0] = hA;
        *(__half2*)&Yh[i1] = hB;
        if (sel) {
            float2 fA = __half22float2(hA), fB = __half22float2(hB);
            *(__half2*)&g_klo[i0] =
                __floats2half2_rn(c[nt][0] - fA.x, c[nt][1] - fA.y);
            *(__half2*)&g_klo[i1] =
                __floats2half2_rn(c[nt][2] - fB.x, c[nt][3] - fB.y);
        }
    }
}

// ---------------------------------------------------------------------------
// V projection (scalar FFMA): Y = X @ Wv -> half, transposed into
// g_vt[b][dim][key], keys pair-permuted.
// ---------------------------------------------------------------------------
__global__ __launch_bounds__(256, 2)
void proj_v(const float* __restrict__ X, const float* __restrict__ W) {
    extern __shared__ float sm[];
    float* sW = sm;               // 128*128
    float* sX = sm + 128 * 128;   // 64 rows, stride 132
    __half* sT = (__half*)sm;     // reuse: 64 x 136 halves

    const int tid = threadIdx.x;
    const long r0 = (long)blockIdx.x * 64;
    const int bb  = (int)(r0 >> 11);
    const int k0  = (int)(r0 & 2047);

    for (int idx = tid; idx < 128 * 32; idx += 256) {
        int row = idx >> 5, k4 = (idx & 31) << 2;
        *(float4*)&sW[row * 128 + k4] = *(const float4*)&W[row * 128 + k4];
    }
    for (int idx = tid; idx < 64 * 32; idx += 256) {
        int row = idx >> 5, k4 = (idx & 31) << 2;
        *(float4*)&sX[row * 132 + k4] = *(const float4*)&X[(r0 + row) * DIM + k4];
    }
    __syncthreads();

    const int tr = tid >> 4;
    const int tc = tid & 15;

    float acc[4][8];
#pragma unroll
    for (int i = 0; i < 4; i++)
#pragma unroll
        for (int j = 0; j < 8; j++) acc[i][j] = 0.f;

#pragma unroll 4
    for (int k = 0; k < 128; k++) {
        float xv[4], wv[8];
#pragma unroll
        for (int i = 0; i < 4; i++) xv[i] = sX[(tr * 4 + i) * 132 + k];
#pragma unroll
        for (int j = 0; j < 8; j++) wv[j] = sW[k * 128 + tc + 16 * j];
#pragma unroll
        for (int i = 0; i < 4; i++)
#pragma unroll
            for (int j = 0; j < 8; j++) acc[i][j] = fmaf(xv[i], wv[j], acc[i][j]);
    }
    __syncthreads();   // done reading sW/sX; reuse as sT

#pragma unroll
    for (int i = 0; i < 4; i++)
#pragma unroll
        for (int j = 0; j < 8; j++)
            sT[(tr * 4 + i) * 136 + tc + 16 * j] = __float2half_rn(acc[i][j]);
    __syncthreads();

    const int w    = tid >> 5;
    const int lane = tid & 31;
    const int pc   = lane >> 3;
    const int pl   = lane & 7;
    const int wd   = permw(pl);
    const int dstk = k0 + pc * 16 + 2 * wd;
#pragma unroll
    for (int m = 0; m < 16; m++) {
        int d = w * 16 + m;
        __half2 h2 = __halves2half2(sT[(2 * lane) * 136 + d],
                                    (__half)sT[(2 * lane + 1) * 136 + d]);
        *(uint32_t*)&g_vt[((long)bb * DIM + d) * SL + dstk] = h2u(h2);
    }
}

// ---------------------------------------------------------------------------
// Flash attention (unchanged): fp16 mma.sync m16n8k16, cp.async double
// buffer. S = Qhi*(Khi+Klo); P single fp16 from registers.
// ---------------------------------------------------------------------------
__global__ __launch_bounds__(256, 1)
void attn_kernel(const int* __restrict__ mask, float* __restrict__ out) {
    extern __shared__ char smem[];
    const uint32_t sb = (uint32_t)__cvta_generic_to_shared(smem);

    const int tid  = threadIdx.x;
    const int w    = tid >> 5;
    const int lane = tid & 31;
    const int g    = lane >> 2;
    const int t    = lane & 3;
    const int b    = blockIdx.x >> 4;
    const int q0   = (blockIdx.x & 15) << 7;

    const __half* gqh = g_qhi + ((long)b * SL + q0) * DIM;
    const __half* gkh = g_khi + (long)b * SL * DIM;
    const __half* gkl = g_klo + (long)b * SL * DIM;
    const __half* gvt = g_vt  + (long)b * DIM * SL;
    const int*    gmk = mask  + (long)b * SL;

    for (int i = tid; i < 2048; i += 256) {
        int r = i >> 4, c = i & 15;
        cpa16(sb + OQH + r * RQ + c * 16, gqh + r * DIM + c * 8);
    }
#define ISSUE_TILE(kt, s)                                                     \
    {                                                                         \
        const int n0_ = (kt) * BK;                                            \
        for (int i = tid; i < 3088; i += 256) {                               \
            if (i < 1024) {                                                   \
                int r = i >> 4, c = i & 15;                                   \
                cpa16(sb + OKH + (s) * (BK * RQ) + r * RQ + c * 16,           \
                      gkh + (long)(n0_ + r) * DIM + c * 8);                   \
            } else if (i < 2048) {                                            \
                int j = i - 1024, r = j >> 4, c = j & 15;                     \
                cpa16(sb + OKL + (s) * (BK * RQ) + r * RQ + c * 16,           \
                      gkl + (long)(n0_ + r) * DIM + c * 8);                   \
            } else if (i < 3072) {                                            \
                int j = i - 2048, r = j >> 3, c = j & 7;                      \
                cpa16(sb + OVT + (s) * (DIM * RV) + r * RV + c * 16,          \
                      gvt + (long)r * SL + n0_ + c * 8);                      \
            } else {                                                          \
                int j = i - 3072;                                             \
                cpa16(sb + OMK + (s) * 256 + j * 16, gmk + n0_ + j * 4);      \
            }                                                                 \
        }                                                                     \
    }
    ISSUE_TILE(0, 0);
    cpa_commit();
    ISSUE_TILE(1, 1);
    cpa_commit();

    const int qrow = (w << 4) + g;
    const char* qh0 = smem + OQH + qrow * RQ;
    const char* qh1 = qh0 + 8 * RQ;

    float o[16][4];
#pragma unroll
    for (int n = 0; n < 16; n++)
#pragma unroll
        for (int j = 0; j < 4; j++) o[n][j] = 0.f;
    float m0 = -1e30f, m1 = -1e30f, l0 = 0.f, l1 = 0.f;
    const float scale = 0.08838834764831845f;

    for (int kt = 0; kt < NT; kt++) {
        const int s = kt & 1;
        if (kt < NT - 1)
            asm volatile("cp.async.wait_group 1;\n" ::: "memory");
        else
            asm volatile("cp.async.wait_group 0;\n" ::: "memory");
        __syncthreads();

        const char* kh = smem + OKH + s * (BK * RQ) + g * RQ;
        const char* kl = smem + OKL + s * (BK * RQ) + g * RQ;
        const char* vb = smem + OVT + s * (DIM * RV) + g * RV;
        const int*  mk = (const int*)(smem + OMK + s * 256);

        float c[8][4];
#pragma unroll
        for (int n = 0; n < 8; n++)
#pragma unroll
            for (int j = 0; j < 4; j++) c[n][j] = 0.f;

#pragma unroll
        for (int kc = 0; kc < 8; kc++) {
            const int off = kc * 32 + t * 8;
            uint2 h0 = *(const uint2*)(qh0 + off);
            uint2 h1 = *(const uint2*)(qh1 + off);
#pragma unroll
            for (int nt = 0; nt < 8; nt++) {
                uint2 bh = *(const uint2*)(kh + nt * (8 * RQ) + off);
                MMA16(c[nt], h0.x, h1.x, h0.y, h1.y, bh.x, bh.y);
            }
#pragma unroll
            for (int nt = 0; nt < 8; nt++) {
                uint2 bl = *(const uint2*)(kl + nt * (8 * RQ) + off);
                MMA16(c[nt], h0.x, h1.x, h0.y, h1.y, bl.x, bl.y);
            }
        }

        float rx0 = -1e30f, rx1 = -1e30f;
#pragma unroll
        for (int nt = 0; nt < 8; nt++) {
            float bs0 = mk[nt * 8 + 2 * t]     ? 0.f : -1e30f;
            float bs1 = mk[nt * 8 + 2 * t + 1] ? 0.f : -1e30f;
            c[nt][0] = fmaf(c[nt][0], scale, bs0);
            c[nt][1] = fmaf(c[nt][1], scale, bs1);
            c[nt][2] = fmaf(c[nt][2], scale, bs0);
            c[nt][3] = fmaf(c[nt][3], scale, bs1);
            rx0 = fmaxf(rx0, fmaxf(c[nt][0], c[nt][1]));
            rx1 = fmaxf(rx1, fmaxf(c[nt][2], c[nt][3]));
        }
        rx0 = fmaxf(rx0, __shfl_xor_sync(0xffffffffu, rx0, 1));
        rx0 = fmaxf(rx0, __shfl_xor_sync(0xffffffffu, rx0, 2));
        rx1 = fmaxf(rx1, __shfl_xor_sync(0xffffffffu, rx1, 1));
        rx1 = fmaxf(rx1, __shfl_xor_sync(0xffffffffu, rx1, 2));

        float mn0 = fmaxf(m0, rx0), mn1 = fmaxf(m1, rx1);
        float al0 = __expf(m0 - mn0), al1 = __expf(m1 - mn1);
        m0 = mn0; m1 = mn1;

#pragma unroll
        for (int n = 0; n < 16; n++) {
            o[n][0] *= al0; o[n][1] *= al0;
            o[n][2] *= al1; o[n][3] *= al1;
        }

#pragma unroll
        for (int kc = 0; kc < 4; kc++) {
            float e0 = __expf(c[2 * kc][0] - m0);
            float e1 = __expf(c[2 * kc][1] - m0);
            float e2 = __expf(c[2 * kc][2] - m1);
            float e3 = __expf(c[2 * kc][3] - m1);
            float e4 = __expf(c[2 * kc + 1][0] - m0);
            float e5 = __expf(c[2 * kc + 1][1] - m0);
            float e6 = __expf(c[2 * kc + 1][2] - m1);
            float e7 = __expf(c[2 * kc + 1][3] - m1);
            c[2 * kc][0] = e0; c[2 * kc][1] = e1;
            c[2 * kc][2] = e2; c[2 * kc][3] = e3;
            c[2 * kc + 1][0] = e4; c[2 * kc + 1][1] = e5;
            c[2 * kc + 1][2] = e6; c[2 * kc + 1][3] = e7;
            uint32_t A0 = h2u(__floats2half2_rn(e0, e1));
            uint32_t A1 = h2u(__floats2half2_rn(e2, e3));
            uint32_t A2 = h2u(__floats2half2_rn(e4, e5));
            uint32_t A3 = h2u(__floats2half2_rn(e6, e7));
            const int off = kc * 32 + t * 8;
#pragma unroll
            for (int nt = 0; nt < 16; nt++) {
                uint2 bv = *(const uint2*)(vb + nt * (8 * RV) + off);
                MMA16(o[nt], A0, A1, A2, A3, bv.x, bv.y);
            }
        }

        float ps0 = 0.f, ps1 = 0.f;
#pragma unroll
        for (int nt = 0; nt < 8; nt++) {
            ps0 += c[nt][0] + c[nt][1];
            ps1 += c[nt][2] + c[nt][3];
        }
        ps0 += __shfl_xor_sync(0xffffffffu, ps0, 1);
        ps0 += __shfl_xor_sync(0xffffffffu, ps0, 2);
        ps1 += __shfl_xor_sync(0xffffffffu, ps1, 1);
        ps1 += __shfl_xor_sync(0xffffffffu, ps1, 2);
        l0 = l0 * al0 + ps0;
        l1 = l1 * al1 + ps1;

        __syncthreads();
        if (kt + 2 < NT) {
            ISSUE_TILE(kt + 2, s);
            cpa_commit();
        }
    }

    float i0 = 1.f / l0, i1 = 1.f / l1;
    long base = ((long)b * SL + q0 + qrow) * DIM;
#pragma unroll
    for (int nt = 0; nt < 16; nt++) {
        float2 r0, r1;
        r0.x = o[nt][0] * i0; r0.y = o[nt][1] * i0;
        r1.x = o[nt][2] * i1; r1.y = o[nt][3] * i1;
        *(float2*)&out[base + nt * 8 + 2 * t] = r0;
        *(float2*)&out[base + 8 * DIM + nt * 8 + 2 * t] = r1;
    }
}

// ---------------------------------------------------------------------------
extern "C" void kernel_launch(void* const* d_in, const int* in_sizes, int n_in,
                              void* d_out, int out_size) {
    (void)in_sizes; (void)n_in; (void)out_size;
    const float* query = (const float*)d_in[0];
    const float* key   = (const float*)d_in[1];
    const float* value = (const float*)d_in[2];
    const float* Wq    = (const float*)d_in[3];
    const float* Wk    = (const float*)d_in[4];
    const float* Wv    = (const float*)d_in[5];
    const int*   mask  = (const int*)d_in[6];
    float* out = (float*)d_out;

    const int projVSmem = (128 * 128 + 64 * 132) * (int)sizeof(float);
    cudaFuncSetAttribute(proj_qk_mma, cudaFuncAttributeMaxDynamicSharedMemorySize, SMEM_PROJQK);
    cudaFuncSetAttribute(proj_v, cudaFuncAttributeMaxDynamicSharedMemorySize, projVSmem);
    cudaFuncSetAttribute(attn_kernel, cudaFuncAttributeMaxDynamicSharedMemorySize, SMEM_ATTN);

    prep_w<<<2, 256>>>(Wq, Wk);
    proj_qk_mma<<<2 * (NB * SL / 128), 256, SMEM_PROJQK>>>(query, key);
    proj_v<<<NB * SL / 64, 256, projVSmem>>>(value, Wv);
    attn_kernel<<<NB * SL / BQ, 256, SMEM_ATTN>>>(mask, out);
}

// round 13
// speedup vs baseline: 1.2628x; 1.2628x over previous
#include <cuda_runtime.h>
#include <cuda_fp16.h>
#include <cstdint>

#define NB  8
#define SL  2048
#define DIM 128
#define BQ  128
#define BK  64
#define NT  (SL / BK)     // 32 K-tiles

// smem byte strides
#define RQ  288           // Q/K row: 128 halves (256B) + 32B pad
#define RV  160           // Vt row: 64 halves (128B) + 32B pad

// attn smem byte offsets (all 16B aligned). Total 152,064 B -> 1 CTA/SM.
#define OQH 0
#define OKH (OQH + BQ * RQ)            // 36864  (2 bufs x 64*288)
#define OKL (OKH + 2 * BK * RQ)        // 73728
#define OVT (OKL + 2 * BK * RQ)        // 110592 (2 bufs x 128*160)
#define OMK (OVT + 2 * DIM * RV)       // 151552 (2 x 256B)
#define SMEM_ATTN (OMK + 2 * 256)      // 152064

// proj_qp_mma smem offsets: Xhi/Xlo/Whi/Wlo, each 128 rows x RQ bytes
#define PXH 0
#define PXL (PXH + 128 * RQ)           // 36864
#define PWH (PXL + 128 * RQ)           // 73728
#define PWL (PWH + 128 * RQ)           // 110592
#define SMEM_PROJQK (PWL + 128 * RQ)   // 147456

// Projected tensors: Qp hi-only; K (raw, converted) hi+lo; V transposed half.
__device__ __half g_qhi[NB * SL * DIM];
__device__ __half g_khi[NB * SL * DIM];
__device__ __half g_klo[NB * SL * DIM];
__device__ __half g_vt [NB * DIM * SL];   // [b][dim][key], key pair-permuted

// M = Wq @ Wk^T, pre-transposed + split: g_mth[d2*128 + kpos(d1)].
__device__ __half g_mth[DIM * DIM];
__device__ __half g_mtl[DIM * DIM];

__device__ __forceinline__ uint32_t h2u(__half2 h) {
    return *reinterpret_cast<uint32_t*>(&h);
}
__device__ __forceinline__ void cpa16(uint32_t saddr, const void* gaddr) {
    asm volatile("cp.async.ca.shared.global [%0], [%1], 16;\n"
                 :: "r"(saddr), "l"(gaddr));
}
__device__ __forceinline__ void cpa_commit() {
    asm volatile("cp.async.commit_group;\n" ::: "memory");
}

#define MMA16(C, A0, A1, A2, A3, B0, B1)                                     \
    asm volatile(                                                            \
        "mma.sync.aligned.m16n8k16.row.col.f32.f16.f16.f32 "                 \
        "{%0,%1,%2,%3},{%4,%5,%6,%7},{%8,%9},{%0,%1,%2,%3};"                 \
        : "+f"(C[0]), "+f"(C[1]), "+f"(C[2]), "+f"(C[3])                     \
        : "r"(A0), "r"(A1), "r"(A2), "r"(A3), "r"(B0), "r"(B1))

// Pair permutation within a 16-col chunk: pair p (cols 2p,2p+1) -> word w.
__host__ __device__ __forceinline__ int permw(int p) {
    return (p < 4) ? (2 * p) : (2 * (p - 4) + 1);
}

// ---------------------------------------------------------------------------
// prep_m: M[d1][d2] = sum_e Wq[d1][e] * Wk[d2][e]  (both row-major 128x128),
// written hi/lo fp16 transposed into g_mth[d2*128 + kpos(d1)] (contraction
// index d1 pair-permuted, matching the proj B-fragment layout).
// 64 CTAs x 2 d1-rows.
// ---------------------------------------------------------------------------
__global__ __launch_bounds__(256, 1)
void prep_m(const float* __restrict__ Wq, const float* __restrict__ Wk) {
    extern __shared__ float sm[];
    float* sWk = sm;                 // 128 x 129 (odd stride: conflict-free)
    float* sWq = sm + 128 * 129;     // 2 x 128

    const int tid = threadIdx.x;
    const int d1base = blockIdx.x * 2;

    for (int i = tid; i < 128 * 32; i += 256) {
        int row = i >> 5, e4 = (i & 31) << 2;
        float4 v = *(const float4*)&Wk[row * 128 + e4];
        sWk[row * 129 + e4 + 0] = v.x;
        sWk[row * 129 + e4 + 1] = v.y;
        sWk[row * 129 + e4 + 2] = v.z;
        sWk[row * 129 + e4 + 3] = v.w;
    }
    if (tid < 64) {
        int r = tid >> 5, e4 = (tid & 31) << 2;
        *(float4*)&sWq[r * 128 + e4] = *(const float4*)&Wq[(d1base + r) * 128 + e4];
    }
    __syncthreads();

    const int dl = tid >> 7;          // 0..1 (warp-uniform)
    const int d2 = tid & 127;
    const int d1 = d1base + dl;

    float m = 0.f;
#pragma unroll 4
    for (int k = 0; k < 128; k++)
        m = fmaf(sWq[dl * 128 + k], sWk[d2 * 129 + k], m);

    __half hi = __float2half_rn(m);
    int kpos = ((d1 >> 4) << 4) + (permw((d1 & 15) >> 1) << 1) + (d1 & 1);
    g_mth[d2 * DIM + kpos] = hi;
    g_mtl[d2 * DIM + kpos] = __float2half_rn(m - __half2float(hi));
}

// ---------------------------------------------------------------------------
// convert_k: raw key fp32 -> hi/lo fp16, columns pair-permuted (physical
// position of logical col c = (c & ~15) + 2*permw((c&15)>>1) + (c&1)).
// Pure streaming, high occupancy, loads batched for MLP.
// ---------------------------------------------------------------------------
__global__ __launch_bounds__(256, 4)
void convert_k(const float* __restrict__ key) {
    const int tid = blockIdx.x * 256 + threadIdx.x;
    float4 v[4];
#pragma unroll
    for (int j = 0; j < 4; j++) {
        long idx = tid + (long)j * 512 * 256;
        v[j] = *(const float4*)&key[idx * 4];
    }
#pragma unroll
    for (int j = 0; j < 4; j++) {
        long idx = tid + (long)j * 512 * 256;
        long row = idx >> 5;
        int  d0  = ((int)idx & 31) << 2;
        __half2 h01 = __floats2half2_rn(v[j].x, v[j].y);
        __half2 h23 = __floats2half2_rn(v[j].z, v[j].w);
        float2 f01 = __half22float2(h01), f23 = __half22float2(h23);
        __half2 l01 = __floats2half2_rn(v[j].x - f01.x, v[j].y - f01.y);
        __half2 l23 = __floats2half2_rn(v[j].z - f23.x, v[j].w - f23.y);
        int p0 = (d0 & 15) >> 1;
        long base = row * DIM + (d0 & ~15);
        *(__half2*)&g_khi[base + 2 * permw(p0)]     = h01;
        *(__half2*)&g_khi[base + 2 * permw(p0 + 1)] = h23;
        *(__half2*)&g_klo[base + 2 * permw(p0)]     = l01;
        *(__half2*)&g_klo[base + 2 * permw(p0 + 1)] = l23;
    }
}

// ---------------------------------------------------------------------------
// Qp projection on tensor cores: Qp = query @ M. CTA = 128 rows, K=128.
// M arrives pre-transposed/split via cp.async. X loads batched (2x8 float4
// in registers before converts) for high MLP. Output: hi fp16 only,
// pair-permuted (same epilogue that produced bit-identical results R10-R12).
// ---------------------------------------------------------------------------
__global__ __launch_bounds__(256, 1)
void proj_qp_mma(const float* __restrict__ Xq) {
    extern __shared__ char smem[];
    const uint32_t sb = (uint32_t)__cvta_generic_to_shared(smem);
    const int blk = blockIdx.x;
    const int tid = threadIdx.x;
    const long r0 = (long)blk * 128;

    // ---- M hi/lo via cp.async: row n = 256B = 16 chunks ----
    for (int i = tid; i < 2 * 128 * 16; i += 256) {
        int half_sel = i >> 11;            // 0 = hi, 1 = lo
        int j = i & 2047, n = j >> 4, c = j & 15;
        const __half* src = (half_sel ? g_mtl : g_mth) + n * DIM + c * 8;
        cpa16(sb + (half_sel ? PWL : PWH) + n * RQ + c * 16, src);
    }
    cpa_commit();

    // ---- X [128 x 128] fp32, batched loads -> hi/lo split, permuted ----
#pragma unroll
    for (int jb = 0; jb < 2; jb++) {
        float4 v[8];
#pragma unroll
        for (int j = 0; j < 8; j++) {
            int i = tid + (jb * 8 + j) * 256;
            int row = i >> 5, d0 = (i & 31) << 2;
            v[j] = *(const float4*)&Xq[(r0 + row) * DIM + d0];
        }
#pragma unroll
        for (int j = 0; j < 8; j++) {
            int i = tid + (jb * 8 + j) * 256;
            int row = i >> 5, d0 = (i & 31) << 2;
            __half2 h01 = __floats2half2_rn(v[j].x, v[j].y);
            __half2 h23 = __floats2half2_rn(v[j].z, v[j].w);
            float2 f01 = __half22float2(h01), f23 = __half22float2(h23);
            __half2 l01 = __floats2half2_rn(v[j].x - f01.x, v[j].y - f01.y);
            __half2 l23 = __floats2half2_rn(v[j].z - f23.x, v[j].w - f23.y);
            int p0 = (d0 & 15) >> 1;
            int base = row * RQ + (d0 >> 4) * 32;
            int o0 = base + permw(p0) * 4;
            int o1 = base + permw(p0 + 1) * 4;
            *(uint32_t*)(smem + PXH + o0) = h2u(h01);
            *(uint32_t*)(smem + PXH + o1) = h2u(h23);
            *(uint32_t*)(smem + PXL + o0) = h2u(l01);
            *(uint32_t*)(smem + PXL + o1) = h2u(l23);
        }
    }
    asm volatile("cp.async.wait_group 0;\n" ::: "memory");
    __syncthreads();

    const int w    = tid >> 5;
    const int lane = tid & 31;
    const int g    = lane >> 2;
    const int t    = lane & 3;
    const int qrow = (w << 4) + g;

    const char* xh0 = smem + PXH + qrow * RQ;
    const char* xh1 = xh0 + 8 * RQ;
    const char* xl0 = smem + PXL + qrow * RQ;
    const char* xl1 = xl0 + 8 * RQ;

    float c[16][4];
#pragma unroll
    for (int n = 0; n < 16; n++)
#pragma unroll
        for (int j = 0; j < 4; j++) c[n][j] = 0.f;

#pragma unroll
    for (int kc = 0; kc < 8; kc++) {
        const int off = kc * 32 + t * 8;
        uint2 a0 = *(const uint2*)(xh0 + off);
        uint2 a1 = *(const uint2*)(xh1 + off);
        uint2 e0 = *(const uint2*)(xl0 + off);
        uint2 e1 = *(const uint2*)(xl1 + off);
#pragma unroll
        for (int nt = 0; nt < 16; nt++) {
            uint2 bh = *(const uint2*)(smem + PWH + (nt * 8 + g) * RQ + off);
            MMA16(c[nt], a0.x, a1.x, a0.y, a1.y, bh.x, bh.y);
        }
#pragma unroll
        for (int nt = 0; nt < 16; nt++) {
            uint2 bh = *(const uint2*)(smem + PWH + (nt * 8 + g) * RQ + off);
            MMA16(c[nt], e0.x, e1.x, e0.y, e1.y, bh.x, bh.y);
        }
#pragma unroll
        for (int nt = 0; nt < 16; nt++) {
            uint2 bl = *(const uint2*)(smem + PWL + (nt * 8 + g) * RQ + off);
            MMA16(c[nt], a0.x, a1.x, a0.y, a1.y, bl.x, bl.y);
        }
    }

    // ---- store hi only: frag col n = 8nt+2t+h -> permuted position ----
#pragma unroll
    for (int nt = 0; nt < 16; nt++) {
        int colb = ((nt >> 1) << 4) + 4 * t + ((nt & 1) << 1);
        long i0 = (r0 + qrow) * DIM + colb;
        long i1 = (r0 + qrow + 8) * DIM + colb;
        *(__half2*)&g_qhi[i0] = __floats2half2_rn(c[nt][0], c[nt][1]);
        *(__half2*)&g_qhi[i1] = __floats2half2_rn(c[nt][2], c[nt][3]);
    }
}

// ---------------------------------------------------------------------------
// V projection (scalar FFMA): Y = X @ Wv -> half, transposed into
// g_vt[b][dim][key], keys pair-permuted.
// ---------------------------------------------------------------------------
__global__ __launch_bounds__(256, 2)
void proj_v(const float* __restrict__ X, const float* __restrict__ W) {
    extern __shared__ float sm[];
    float* sW = sm;               // 128*128
    float* sX = sm + 128 * 128;   // 64 rows, stride 132
    __half* sT = (__half*)sm;     // reuse: 64 x 136 halves

    const int tid = threadIdx.x;
    const long r0 = (long)blockIdx.x * 64;
    const int bb  = (int)(r0 >> 11);
    const int k0  = (int)(r0 & 2047);

    for (int idx = tid; idx < 128 * 32; idx += 256) {
        int row = idx >> 5, k4 = (idx & 31) << 2;
        *(float4*)&sW[row * 128 + k4] = *(const float4*)&W[row * 128 + k4];
    }
    for (int idx = tid; idx < 64 * 32; idx += 256) {
        int row = idx >> 5, k4 = (idx & 31) << 2;
        *(float4*)&sX[row * 132 + k4] = *(const float4*)&X[(r0 + row) * DIM + k4];
    }
    __syncthreads();

    const int tr = tid >> 4;
    const int tc = tid & 15;

    float acc[4][8];
#pragma unroll
    for (int i = 0; i < 4; i++)
#pragma unroll
        for (int j = 0; j < 8; j++) acc[i][j] = 0.f;

#pragma unroll 4
    for (int k = 0; k < 128; k++) {
        float xv[4], wv[8];
#pragma unroll
        for (int i = 0; i < 4; i++) xv[i] = sX[(tr * 4 + i) * 132 + k];
#pragma unroll
        for (int j = 0; j < 8; j++) wv[j] = sW[k * 128 + tc + 16 * j];
#pragma unroll
        for (int i = 0; i < 4; i++)
#pragma unroll
            for (int j = 0; j < 8; j++) acc[i][j] = fmaf(xv[i], wv[j], acc[i][j]);
    }
    __syncthreads();   // done reading sW/sX; reuse as sT

#pragma unroll
    for (int i = 0; i < 4; i++)
#pragma unroll
        for (int j = 0; j < 8; j++)
            sT[(tr * 4 + i) * 136 + tc + 16 * j] = __float2half_rn(acc[i][j]);
    __syncthreads();

    const int w    = tid >> 5;
    const int lane = tid & 31;
    const int pc   = lane >> 3;
    const int pl   = lane & 7;
    const int wd   = permw(pl);
    const int dstk = k0 + pc * 16 + 2 * wd;
#pragma unroll
    for (int m = 0; m < 16; m++) {
        int d = w * 16 + m;
        __half2 h2 = __halves2half2(sT[(2 * lane) * 136 + d],
                                    (__half)sT[(2 * lane + 1) * 136 + d]);
        *(uint32_t*)&g_vt[((long)bb * DIM + d) * SL + dstk] = h2u(h2);
    }
}

// ---------------------------------------------------------------------------
// Flash attention (unchanged): fp16 mma.sync m16n8k16, cp.async double
// buffer. S = Qphi*(Khi+Klo); P single fp16 from registers.
// ---------------------------------------------------------------------------
__global__ __launch_bounds__(256, 1)
void attn_kernel(const int* __restrict__ mask, float* __restrict__ out) {
    extern __shared__ char smem[];
    const uint32_t sb = (uint32_t)__cvta_generic_to_shared(smem);

    const int tid  = threadIdx.x;
    const int w    = tid >> 5;
    const int lane = tid & 31;
    const int g    = lane >> 2;
    const int t    = lane & 3;
    const int b    = blockIdx.x >> 4;
    const int q0   = (blockIdx.x & 15) << 7;

    const __half* gqh = g_qhi + ((long)b * SL + q0) * DIM;
    const __half* gkh = g_khi + (long)b * SL * DIM;
    const __half* gkl = g_klo + (long)b * SL * DIM;
    const __half* gvt = g_vt  + (long)b * DIM * SL;
    const int*    gmk = mask  + (long)b * SL;

    for (int i = tid; i < 2048; i += 256) {
        int r = i >> 4, c = i & 15;
        cpa16(sb + OQH + r * RQ + c * 16, gqh + r * DIM + c * 8);
    }
#define ISSUE_TILE(kt, s)                                                     \
    {                                                                         \
        const int n0_ = (kt) * BK;                                            \
        for (int i = tid; i < 3088; i += 256) {                               \
            if (i < 1024) {                                                   \
                int r = i >> 4, c = i & 15;                                   \
                cpa16(sb + OKH + (s) * (BK * RQ) + r * RQ + c * 16,           \
                      gkh + (long)(n0_ + r) * DIM + c * 8);                   \
            } else if (i < 2048) {                                            \
                int j = i - 1024, r = j >> 4, c = j & 15;                     \
                cpa16(sb + OKL + (s) * (BK * RQ) + r * RQ + c * 16,           \
                      gkl + (long)(n0_ + r) * DIM + c * 8);                   \
            } else if (i < 3072) {                                            \
                int j = i - 2048, r = j >> 3, c = j & 7;                      \
                cpa16(sb + OVT + (s) * (DIM * RV) + r * RV + c * 16,          \
                      gvt + (long)r * SL + n0_ + c * 8);                      \
            } else {                                                          \
                int j = i - 3072;                                             \
                cpa16(sb + OMK + (s) * 256 + j * 16, gmk + n0_ + j * 4);      \
            }                                                                 \
        }                                                                     \
    }
    ISSUE_TILE(0, 0);
    cpa_commit();
    ISSUE_TILE(1, 1);
    cpa_commit();

    const int qrow = (w << 4) + g;
    const char* qh0 = smem + OQH + qrow * RQ;
    const char* qh1 = qh0 + 8 * RQ;

    float o[16][4];
#pragma unroll
    for (int n = 0; n < 16; n++)
#pragma unroll
        for (int j = 0; j < 4; j++) o[n][j] = 0.f;
    float m0 = -1e30f, m1 = -1e30f, l0 = 0.f, l1 = 0.f;
    const float scale = 0.08838834764831845f;

    for (int kt = 0; kt < NT; kt++) {
        const int s = kt & 1;
        if (kt < NT - 1)
            asm volatile("cp.async.wait_group 1;\n" ::: "memory");
        else
            asm volatile("cp.async.wait_group 0;\n" ::: "memory");
        __syncthreads();

        const char* kh = smem + OKH + s * (BK * RQ) + g * RQ;
        const char* kl = smem + OKL + s * (BK * RQ) + g * RQ;
        const char* vb = smem + OVT + s * (DIM * RV) + g * RV;
        const int*  mk = (const int*)(smem + OMK + s * 256);

        float c[8][4];
#pragma unroll
        for (int n = 0; n < 8; n++)
#pragma unroll
            for (int j = 0; j < 4; j++) c[n][j] = 0.f;

#pragma unroll
        for (int kc = 0; kc < 8; kc++) {
            const int off = kc * 32 + t * 8;
            uint2 h0 = *(const uint2*)(qh0 + off);
            uint2 h1 = *(const uint2*)(qh1 + off);
#pragma unroll
            for (int nt = 0; nt < 8; nt++) {
                uint2 bh = *(const uint2*)(kh + nt * (8 * RQ) + off);
                MMA16(c[nt], h0.x, h1.x, h0.y, h1.y, bh.x, bh.y);
            }
#pragma unroll
            for (int nt = 0; nt < 8; nt++) {
                uint2 bl = *(const uint2*)(kl + nt * (8 * RQ) + off);
                MMA16(c[nt], h0.x, h1.x, h0.y, h1.y, bl.x, bl.y);
            }
        }

        float rx0 = -1e30f, rx1 = -1e30f;
#pragma unroll
        for (int nt = 0; nt < 8; nt++) {
            float bs0 = mk[nt * 8 + 2 * t]     ? 0.f : -1e30f;
            float bs1 = mk[nt * 8 + 2 * t + 1] ? 0.f : -1e30f;
            c[nt][0] = fmaf(c[nt][0], scale, bs0);
            c[nt][1] = fmaf(c[nt][1], scale, bs1);
            c[nt][2] = fmaf(c[nt][2], scale, bs0);
            c[nt][3] = fmaf(c[nt][3], scale, bs1);
            rx0 = fmaxf(rx0, fmaxf(c[nt][0], c[nt][1]));
            rx1 = fmaxf(rx1, fmaxf(c[nt][2], c[nt][3]));
        }
        rx0 = fmaxf(rx0, __shfl_xor_sync(0xffffffffu, rx0, 1));
        rx0 = fmaxf(rx0, __shfl_xor_sync(0xffffffffu, rx0, 2));
        rx1 = fmaxf(rx1, __shfl_xor_sync(0xffffffffu, rx1, 1));
        rx1 = fmaxf(rx1, __shfl_xor_sync(0xffffffffu, rx1, 2));

        float mn0 = fmaxf(m0, rx0), mn1 = fmaxf(m1, rx1);
        float al0 = __expf(m0 - mn0), al1 = __expf(m1 - mn1);
        m0 = mn0; m1 = mn1;

#pragma unroll
        for (int n = 0; n < 16; n++) {
            o[n][0] *= al0; o[n][1] *= al0;
            o[n][2] *= al1; o[n][3] *= al1;
        }

#pragma unroll
        for (int kc = 0; kc < 4; kc++) {
            float e0 = __expf(c[2 * kc][0] - m0);
            float e1 = __expf(c[2 * kc][1] - m0);
            float e2 = __expf(c[2 * kc][2] - m1);
            float e3 = __expf(c[2 * kc][3] - m1);
            float e4 = __expf(c[2 * kc + 1][0] - m0);
            float e5 = __expf(c[2 * kc + 1][1] - m0);
            float e6 = __expf(c[2 * kc + 1][2] - m1);
            float e7 = __expf(c[2 * kc + 1][3] - m1);
            c[2 * kc][0] = e0; c[2 * kc][1] = e1;
            c[2 * kc][2] = e2; c[2 * kc][3] = e3;
            c[2 * kc + 1][0] = e4; c[2 * kc + 1][1] = e5;
            c[2 * kc + 1][2] = e6; c[2 * kc + 1][3] = e7;
            uint32_t A0 = h2u(__floats2half2_rn(e0, e1));
            uint32_t A1 = h2u(__floats2half2_rn(e2, e3));
            uint32_t A2 = h2u(__floats2half2_rn(e4, e5));
            uint32_t A3 = h2u(__floats2half2_rn(e6, e7));
            const int off = kc * 32 + t * 8;
#pragma unroll
            for (int nt = 0; nt < 16; nt++) {
                uint2 bv = *(const uint2*)(vb + nt * (8 * RV) + off);
                MMA16(o[nt], A0, A1, A2, A3, bv.x, bv.y);
            }
        }

        float ps0 = 0.f, ps1 = 0.f;
#pragma unroll
        for (int nt = 0; nt < 8; nt++) {
            ps0 += c[nt][0] + c[nt][1];
            ps1 += c[nt][2] + c[nt][3];
        }
        ps0 += __shfl_xor_sync(0xffffffffu, ps0, 1);
        ps0 += __shfl_xor_sync(0xffffffffu, ps0, 2);
        ps1 += __shfl_xor_sync(0xffffffffu, ps1, 1);
        ps1 += __shfl_xor_sync(0xffffffffu, ps1, 2);
        l0 = l0 * al0 + ps0;
        l1 = l1 * al1 + ps1;

        __syncthreads();
        if (kt + 2 < NT) {
            ISSUE_TILE(kt + 2, s);
            cpa_commit();
        }
    }

    float i0 = 1.f / l0, i1 = 1.f / l1;
    long base = ((long)b * SL + q0 + qrow) * DIM;
#pragma unroll
    for (int nt = 0; nt < 16; nt++) {
        float2 r0, r1;
        r0.x = o[nt][0] * i0; r0.y = o[nt][1] * i0;
        r1.x = o[nt][2] * i1; r1.y = o[nt][3] * i1;
        *(float2*)&out[base + nt * 8 + 2 * t] = r0;
        *(float2*)&out[base + 8 * DIM + nt * 8 + 2 * t] = r1;
    }
}

// ---------------------------------------------------------------------------
extern "C" void kernel_launch(void* const* d_in, const int* in_sizes, int n_in,
                              void* d_out, int out_size) {
    (void)in_sizes; (void)n_in; (void)out_size;
    const float* query = (const float*)d_in[0];
    const float* key   = (const float*)d_in[1];
    const float* value = (const float*)d_in[2];
    const float* Wq    = (const float*)d_in[3];
    const float* Wk    = (const float*)d_in[4];
    const float* Wv    = (const float*)d_in[5];
    const int*   mask  = (const int*)d_in[6];
    float* out = (float*)d_out;

    const int prepMSmem = (128 * 129 + 2 * 128) * (int)sizeof(float);  // 67072
    const int projVSmem = (128 * 128 + 64 * 132) * (int)sizeof(float);
    cudaFuncSetAttribute(prep_m, cudaFuncAttributeMaxDynamicSharedMemorySize, prepMSmem);
    cudaFuncSetAttribute(proj_qp_mma, cudaFuncAttributeMaxDynamicSharedMemorySize, SMEM_PROJQK);
    cudaFuncSetAttribute(proj_v, cudaFuncAttributeMaxDynamicSharedMemorySize, projVSmem);
    cudaFuncSetAttribute(attn_kernel, cudaFuncAttributeMaxDynamicSharedMemorySize, SMEM_ATTN);

    prep_m<<<64, 256, prepMSmem>>>(Wq, Wk);
    convert_k<<<512, 256>>>(key);
    proj_qp_mma<<<NB * SL / 128, 256, SMEM_PROJQK>>>(query);
    proj_v<<<NB * SL / 64, 256, projVSmem>>>(value, Wv);
    attn_kernel<<<NB * SL / BQ, 256, SMEM_ATTN>>>(mask, out);
}